// round 8
// baseline (speedup 1.0000x reference)
#include <cuda_runtime.h>

// DynamicTimeStretch: out[t] = (alpha*n[idx+1] + (1-alpha)*n[idx])^2,
// n[j] = |spec[j]|. Phase accumulation cancels under abs()^2.
// Persistent blocks; next row staged in REGISTERS (LDG in flight during
// consume) — no smem round-trip for raw data, only the norms array.

#define N_ROWS (16 * 513)     // 8208
#define T_IN 2048
#define N_OUT 2276
#define N_OUT4 (N_OUT / 4)    // 569
#define RATE 0.9f
#define THREADS 288
#define GRID (148 * 7)        // 1036 persistent blocks, ~8 rows each

__global__ void __launch_bounds__(THREADS)
dts_kernel(const float* __restrict__ xr,
           const float* __restrict__ xi,
           float* __restrict__ out)
{
    __shared__ float n[T_IN + 4];   // norms + sentinel n[2048]=0

    const int tid = threadIdx.x;
    if (tid == 0) n[T_IN] = 0.0f;   // persists across rows

    // Register staging for one row: 512 float4 per input over 288 threads.
    // v=0: all threads (tid<512 always), v=1: tid<224.
    float4 Rr[2], Ri[2];

    int row = blockIdx.x;

    // Prologue: stage first row into registers.
    {
        const float4* r4 = (const float4*)(xr + (long)row * T_IN);
        const float4* i4 = (const float4*)(xi + (long)row * T_IN);
        Rr[0] = __ldcs(r4 + tid);
        Ri[0] = __ldcs(i4 + tid);
        if (tid < 224) {
            Rr[1] = __ldcs(r4 + tid + THREADS);
            Ri[1] = __ldcs(i4 + tid + THREADS);
        }
    }

    for (; row < N_ROWS; row += GRID) {
        __syncthreads();            // previous consume done reading n (WAR)

        // Norms: registers -> n
        #pragma unroll
        for (int v = 0; v < 2; v++) {
            const int j4 = tid + v * THREADS;
            if (v == 0 || tid < 224) {
                const float4 rr = Rr[v], ii = Ri[v];
                float4 s;
                s.x = sqrtf(fmaf(rr.x, rr.x, ii.x * ii.x));
                s.y = sqrtf(fmaf(rr.y, rr.y, ii.y * ii.y));
                s.z = sqrtf(fmaf(rr.z, rr.z, ii.z * ii.z));
                s.w = sqrtf(fmaf(rr.w, rr.w, ii.w * ii.w));
                ((float4*)n)[j4] = s;
            }
        }
        __syncthreads();            // n ready

        // Issue next row's LDGs now — in flight during consume below.
        const int nrow = row + GRID;
        if (nrow < N_ROWS) {
            const float4* r4 = (const float4*)(xr + (long)nrow * T_IN);
            const float4* i4 = (const float4*)(xi + (long)nrow * T_IN);
            Rr[0] = __ldcs(r4 + tid);
            Ri[0] = __ldcs(i4 + tid);
            if (tid < 224) {
                Rr[1] = __ldcs(r4 + tid + THREADS);
                Ri[1] = __ldcs(i4 + tid + THREADS);
            }
        }

        // Consume: 569 float4 outputs over 288 threads (2 iters, 98.8% eff)
        float* orow = out + (long)row * N_OUT;
        #pragma unroll
        for (int v = 0; v < 2; v++) {
            const int o4 = tid + v * THREADS;
            if (o4 < N_OUT4) {
                float4 res;
                #pragma unroll
                for (int k = 0; k < 4; k++) {
                    const int t = o4 * 4 + k;
                    // Match jax f32 arithmetic exactly
                    const float ts = (float)t * RATE;
                    const int idx = (int)ts;
                    const float a = ts - (float)idx;
                    const float m = fmaf(a, n[idx + 1], (1.0f - a) * n[idx]);
                    ((float*)&res)[k] = m * m;
                }
                __stcs((float4*)orow + o4, res);
            }
        }
    }
}

extern "C" void kernel_launch(void* const* d_in, const int* in_sizes, int n_in,
                              void* d_out, int out_size)
{
    const float* xr = (const float*)d_in[0];
    const float* xi = (const float*)d_in[1];
    float* out = (float*)d_out;

    dts_kernel<<<GRID, THREADS>>>(xr, xi, out);
}